// round 1
// baseline (speedup 1.0000x reference)
#include <cuda_runtime.h>
#include <math.h>

#define BB 4
#define SS 2048
#define VV 64
#define DD 1024
#define PP 8
#define HH 42
#define KK 49152
#define EPSF 1e-12f
#define COSEPS 1e-8f
#define SQRT_S 45.254834f   // sqrt(2048)

// ---------------- scratch (static device globals; no allocs allowed) ----------------
__device__ float g_u[PP * DD];            // sign-ish vectors e/max(2|e|,eps)
__device__ float g_w1t[HH * DD];          // w1 transposed [H][D]
__device__ float g_n[PP * BB * SS];       // n values
__device__ float g_wsm[PP * BB * SS];     // softmax weights over s
__device__ float g_avp[8 * PP * BB * DD]; // a_v partials per s-chunk
__device__ float g_av[PP * BB * DD];      // a_v
__device__ float g_gate[BB * PP];         // final gates
__device__ float g_hbar[BB * VV * HH];    // gate-combined hidden

// ---------------- kernel 0: prep (u, w1 transpose) ----------------
__global__ void kprep(const float* __restrict__ lora, const float* __restrict__ w1) {
    int i = blockIdx.x * 256 + threadIdx.x;   // grid covers 43008 exactly
    if (i < PP * DD) {
        float e = lora[i];
        g_u[i] = e / fmaxf(2.0f * fabsf(e), EPSF);
    }
    if (i < HH * DD) {
        int h = i / DD, d = i % DD;
        g_w1t[i] = w1[d * HH + h];
    }
}

// ---------------- kernel 1: per-(b,s) row norm + 8 dots -> n[p,b,s] ----------------
__global__ __launch_bounds__(256) void knorm(const float* __restrict__ ctx) {
    __shared__ float s_u[PP * DD];
    for (int i = threadIdx.x; i < PP * DD; i += 256) s_u[i] = g_u[i];
    __syncthreads();
    int warp = threadIdx.x >> 5, lane = threadIdx.x & 31;
    int row = blockIdx.x * 8 + warp;          // [0, B*S)
    int b = row / SS, s = row % SS;
    const float4* x4 = reinterpret_cast<const float4*>(ctx + (size_t)row * DD);
    float nrm2 = 0.f;
    float dot[PP];
#pragma unroll
    for (int p = 0; p < PP; p++) dot[p] = 0.f;
#pragma unroll
    for (int it = 0; it < 8; it++) {
        int q = lane + it * 32;               // float4 index 0..255
        float4 x = x4[q];
        nrm2 += x.x * x.x + x.y * x.y + x.z * x.z + x.w * x.w;
#pragma unroll
        for (int p = 0; p < PP; p++) {
            float4 u = reinterpret_cast<const float4*>(s_u + p * DD)[q];
            dot[p] += x.x * u.x + x.y * u.y + x.z * u.z + x.w * u.w;
        }
    }
#pragma unroll
    for (int off = 16; off; off >>= 1) {
        nrm2 += __shfl_xor_sync(0xffffffffu, nrm2, off);
#pragma unroll
        for (int p = 0; p < PP; p++) dot[p] += __shfl_xor_sync(0xffffffffu, dot[p], off);
    }
    if (lane < PP) {
        float dl = 0.f;
#pragma unroll
        for (int p = 0; p < PP; p++) if (lane == p) dl = dot[p];
        float denom = fmaxf(sqrtf(nrm2), EPSF);
        float v = dl / denom;
        float c = fmaxf(v, 0.f);
        float n = c / fmaxf(SQRT_S * c, EPSF);
        g_n[((size_t)lane * BB + b) * SS + s] = n;
    }
}

// ---------------- kernel 2: softmax over s (per p,b) -> weights ----------------
__global__ __launch_bounds__(256) void ksoft() {
    __shared__ float sn[SS];
    __shared__ float red[256];
    int pb = blockIdx.x;
    int t = threadIdx.x;
    const float* np = g_n + (size_t)pb * SS;
    float m = -1e30f;
    for (int i = t; i < SS; i += 256) { float v = np[i]; sn[i] = v; m = fmaxf(m, v); }
    red[t] = m; __syncthreads();
    for (int o = 128; o; o >>= 1) { if (t < o) red[t] = fmaxf(red[t], red[t + o]); __syncthreads(); }
    m = red[0]; __syncthreads();
    float sum = 0.f;
    for (int i = t; i < SS; i += 256) sum += expf(sn[i] - m);
    red[t] = sum; __syncthreads();
    for (int o = 128; o; o >>= 1) { if (t < o) red[t] += red[t + o]; __syncthreads(); }
    float inv = 1.0f / red[0];
    for (int i = t; i < SS; i += 256) g_wsm[(size_t)pb * SS + i] = expf(sn[i] - m) * inv;
}

// ---------------- kernel 3: a_v partials: sum_s w[p,b,s] * ctx[b,s,d] ----------------
__global__ __launch_bounds__(128) void kavp(const float* __restrict__ ctx) {
    __shared__ float ws[256 * PP];
    int dchunk = blockIdx.x, schunk = blockIdx.y, b = blockIdx.z;
    int t = threadIdx.x;
    for (int i = t; i < 256 * PP; i += 128) {
        int sl = i >> 3, p = i & 7;
        ws[i] = g_wsm[((size_t)p * BB + b) * SS + schunk * 256 + sl];
    }
    __syncthreads();
    int d = dchunk * 128 + t;
    float acc[PP];
#pragma unroll
    for (int p = 0; p < PP; p++) acc[p] = 0.f;
    const float* cp = ctx + ((size_t)b * SS + schunk * 256) * DD + d;
    for (int sl = 0; sl < 256; sl++) {
        float x = cp[(size_t)sl * DD];
#pragma unroll
        for (int p = 0; p < PP; p++) acc[p] += ws[sl * 8 + p] * x;
    }
#pragma unroll
    for (int p = 0; p < PP; p++)
        g_avp[(((size_t)schunk * PP + p) * BB + b) * DD + d] = acc[p];
}

// ---------------- kernel 4: reduce partials ----------------
__global__ void kavred() {
    int i = blockIdx.x * 256 + threadIdx.x;   // PP*BB*DD = 32768
    float s = 0.f;
#pragma unroll
    for (int c = 0; c < 8; c++) s += g_avp[(size_t)c * PP * BB * DD + i];
    g_av[i] = s;
}

// ---------------- kernel 5: cos + double softmax -> gates ----------------
__global__ __launch_bounds__(1024) void kgate(const float* __restrict__ lora) {
    __shared__ float cs[PP * BB];
    int t = threadIdx.x, warp = t >> 5, lane = t & 31;
    int p = warp >> 2, b = warp & 3;
    float dot = 0.f, an2 = 0.f, en2 = 0.f;
    const float* e = lora + p * DD;
    const float* a = g_av + ((size_t)p * BB + b) * DD;
    for (int d = lane; d < DD; d += 32) {
        float ev = e[d], av = a[d];
        dot += ev * av; an2 += av * av; en2 += ev * ev;
    }
#pragma unroll
    for (int o = 16; o; o >>= 1) {
        dot += __shfl_xor_sync(0xffffffffu, dot, o);
        an2 += __shfl_xor_sync(0xffffffffu, an2, o);
        en2 += __shfl_xor_sync(0xffffffffu, en2, o);
    }
    if (lane == 0) cs[p * BB + b] = dot / fmaxf(sqrtf(en2) * sqrtf(an2), COSEPS);
    __syncthreads();
    if (t < BB) {
        int bb = t;
        float x[PP], m = -1e30f;
#pragma unroll
        for (int pp = 0; pp < PP; pp++) { x[pp] = cs[pp * BB + bb]; m = fmaxf(m, x[pp]); }
        float z = 0.f;
#pragma unroll
        for (int pp = 0; pp < PP; pp++) { x[pp] = expf(x[pp] - m); z += x[pp]; }
#pragma unroll
        for (int pp = 0; pp < PP; pp++) x[pp] /= z;      // s_t
        m = -1e30f;
#pragma unroll
        for (int pp = 0; pp < PP; pp++) m = fmaxf(m, x[pp]);
        z = 0.f;
#pragma unroll
        for (int pp = 0; pp < PP; pp++) { x[pp] = expf(x[pp] - m); z += x[pp]; }
#pragma unroll
        for (int pp = 0; pp < PP; pp++) g_gate[bb * PP + pp] = x[pp] / z;  // gate
    }
}

// ---------------- kernel 6: hbar[b,v,h] = sum_p gate * tanh(tok@w1 + b1) ----------------
__global__ __launch_bounds__(256) void khbar(const int* __restrict__ prefix,
                                             const float* __restrict__ tables,
                                             const float* __restrict__ b1) {
    __shared__ float tok[DD];
    int bv = blockIdx.x;
    int b = bv / VV;
    int t = threadIdx.x, warp = t >> 5, lane = t & 31;
    int pf = prefix[bv];
    float hacc[6];
#pragma unroll
    for (int j = 0; j < 6; j++) hacc[j] = 0.f;
    for (int p = 0; p < PP; p++) {
        __syncthreads();
        const float* src = tables + ((size_t)p * VV + pf) * DD;
        for (int i = t; i < DD; i += 256) tok[i] = src[i];
        __syncthreads();
        float gpb = g_gate[b * PP + p];
#pragma unroll
        for (int j = 0; j < 6; j++) {
            int h = warp + j * 8;
            if (h < HH) {
                const float4* wrow = reinterpret_cast<const float4*>(g_w1t + (size_t)h * DD);
                const float4* tk4 = reinterpret_cast<const float4*>(tok);
                float dot = 0.f;
#pragma unroll
                for (int it = 0; it < 8; it++) {
                    float4 wv = wrow[lane + it * 32];
                    float4 tv = tk4[lane + it * 32];
                    dot += wv.x * tv.x + wv.y * tv.y + wv.z * tv.z + wv.w * tv.w;
                }
#pragma unroll
                for (int o = 16; o; o >>= 1) dot += __shfl_xor_sync(0xffffffffu, dot, o);
                hacc[j] += gpb * tanhf(dot + b1[h]);
            }
        }
    }
    if (lane == 0) {
#pragma unroll
        for (int j = 0; j < 6; j++) {
            int h = warp + j * 8;
            if (h < HH) g_hbar[(size_t)bv * HH + h] = hacc[j];
        }
    }
}

// ---------------- kernel 7: out = hbar @ w2 + b2 (packed f32x2 FFMA2) ----------------
__device__ __forceinline__ unsigned long long fma2(unsigned long long a,
                                                   unsigned long long b,
                                                   unsigned long long c) {
    unsigned long long d;
    asm("fma.rn.f32x2 %0, %1, %2, %3;" : "=l"(d) : "l"(a), "l"(b), "l"(c));
    return d;
}

__global__ __launch_bounds__(128) void kout(const float* __restrict__ w2,
                                            const float* __restrict__ b2,
                                            float* __restrict__ out) {
    __shared__ unsigned long long hb2[64 * HH];   // hbar duplicated {v,v}
    int r0 = blockIdx.y * 64;
    int t = threadIdx.x;
    for (int i = t; i < 64 * HH; i += 128) {
        float v = g_hbar[(size_t)(r0 + i / HH) * HH + (i % HH)];
        float2 d2 = make_float2(v, v);
        hb2[i] = *reinterpret_cast<unsigned long long*>(&d2);
    }
    __syncthreads();
    int kp = blockIdx.x * 256 + t * 2;
    unsigned long long wcol[HH];
#pragma unroll
    for (int h = 0; h < HH; h++) {
        float2 wv = *reinterpret_cast<const float2*>(w2 + (size_t)h * KK + kp);
        wcol[h] = *reinterpret_cast<unsigned long long*>(&wv);
    }
    float2 bv = *reinterpret_cast<const float2*>(b2 + kp);
    unsigned long long binit = *reinterpret_cast<unsigned long long*>(&bv);
    for (int rg = 0; rg < 64; rg += 4) {
        unsigned long long a0 = binit, a1 = binit, a2 = binit, a3 = binit;
#pragma unroll
        for (int h = 0; h < HH; h++) {
            a0 = fma2(wcol[h], hb2[(rg + 0) * HH + h], a0);
            a1 = fma2(wcol[h], hb2[(rg + 1) * HH + h], a1);
            a2 = fma2(wcol[h], hb2[(rg + 2) * HH + h], a2);
            a3 = fma2(wcol[h], hb2[(rg + 3) * HH + h], a3);
        }
        *reinterpret_cast<float2*>(out + (size_t)(r0 + rg + 0) * KK + kp) = *reinterpret_cast<float2*>(&a0);
        *reinterpret_cast<float2*>(out + (size_t)(r0 + rg + 1) * KK + kp) = *reinterpret_cast<float2*>(&a1);
        *reinterpret_cast<float2*>(out + (size_t)(r0 + rg + 2) * KK + kp) = *reinterpret_cast<float2*>(&a2);
        *reinterpret_cast<float2*>(out + (size_t)(r0 + rg + 3) * KK + kp) = *reinterpret_cast<float2*>(&a3);
    }
}

// ---------------- launcher ----------------
extern "C" void kernel_launch(void* const* d_in, const int* in_sizes, int n_in,
                              void* d_out, int out_size) {
    const int* prefix = nullptr;
    const float *ctx = nullptr, *tables = nullptr, *lora = nullptr;
    const float *w1 = nullptr, *b1 = nullptr, *w2 = nullptr, *b2 = nullptr;
    for (int i = 0; i < n_in; i++) {
        switch (in_sizes[i]) {
            case 256:     prefix = (const int*)d_in[i];   break;  // (B,V) int32
            case 8388608: ctx    = (const float*)d_in[i]; break;  // (B,S,D)
            case 524288:  tables = (const float*)d_in[i]; break;  // (P,V,D)
            case 8192:    lora   = (const float*)d_in[i]; break;  // (P,D)
            case 43008:   w1     = (const float*)d_in[i]; break;  // (D,H)
            case 42:      b1     = (const float*)d_in[i]; break;  // (H,)
            case 2064384: w2     = (const float*)d_in[i]; break;  // (H,K)
            case 49152:   b2     = (const float*)d_in[i]; break;  // (K,)
        }
    }
    float* out = (float*)d_out;

    kprep<<<168, 256>>>(lora, w1);
    knorm<<<1024, 256>>>(ctx);
    ksoft<<<32, 256>>>();
    kavp<<<dim3(8, 8, 4), 128>>>(ctx);
    kavred<<<128, 256>>>();
    kgate<<<1, 1024>>>(lora);
    khbar<<<256, 256>>>(prefix, tables, b1);
    kout<<<dim3(KK / 256, 4), 128>>>(w2, b2, out);
}

// round 2
// speedup vs baseline: 1.6724x; 1.6724x over previous
#include <cuda_runtime.h>
#include <math.h>

#define BB 4
#define SS 2048
#define VV 64
#define DD 1024
#define PP 8
#define HH 42
#define KK 49152
#define EPSF 1e-12f
#define COSEPS 1e-8f
#define SQRT_S 45.254834f   // sqrt(2048)
#define NSC 64              // s-chunks in kavp (32 s each)

// ---------------- scratch (static device globals; no allocs allowed) ----------------
__device__ float g_u[PP * DD];              // sign-ish vectors e/max(2|e|,eps)
__device__ float g_w1t[HH * DD];            // w1 transposed [H][D]
__device__ float g_n[PP * BB * SS];         // n values
__device__ float g_wsm[PP * BB * SS];       // softmax weights over s
__device__ float g_avp[NSC * PP * BB * DD]; // a_v partials per s-chunk (8MB)
__device__ float g_av[PP * BB * DD];        // a_v
__device__ float g_gate[BB * PP];           // final gates
__device__ float g_hbar[BB * VV * HH];      // gate-combined hidden

// ---------------- kernel 0: prep (u, w1 transpose) ----------------
__global__ void kprep(const float* __restrict__ lora, const float* __restrict__ w1) {
    int i = blockIdx.x * 256 + threadIdx.x;   // grid covers 43008 exactly
    if (i < PP * DD) {
        float e = lora[i];
        g_u[i] = e / fmaxf(2.0f * fabsf(e), EPSF);
    }
    if (i < HH * DD) {
        int h = i / DD, d = i % DD;
        g_w1t[i] = w1[d * HH + h];
    }
}

// ---------------- kernel 1: per-(b,s) row norm + 8 dots -> n[p,b,s] ----------------
__global__ __launch_bounds__(256) void knorm(const float* __restrict__ ctx) {
    __shared__ float s_u[PP * DD];
    for (int i = threadIdx.x; i < PP * DD; i += 256) s_u[i] = g_u[i];
    __syncthreads();
    int warp = threadIdx.x >> 5, lane = threadIdx.x & 31;
    int row = blockIdx.x * 8 + warp;          // [0, B*S)
    int b = row / SS, s = row % SS;
    const float4* x4 = reinterpret_cast<const float4*>(ctx + (size_t)row * DD);
    float nrm2 = 0.f;
    float dot[PP];
#pragma unroll
    for (int p = 0; p < PP; p++) dot[p] = 0.f;
#pragma unroll
    for (int it = 0; it < 8; it++) {
        int q = lane + it * 32;               // float4 index 0..255
        float4 x = x4[q];
        nrm2 += x.x * x.x + x.y * x.y + x.z * x.z + x.w * x.w;
#pragma unroll
        for (int p = 0; p < PP; p++) {
            float4 u = reinterpret_cast<const float4*>(s_u + p * DD)[q];
            dot[p] += x.x * u.x + x.y * u.y + x.z * u.z + x.w * u.w;
        }
    }
#pragma unroll
    for (int off = 16; off; off >>= 1) {
        nrm2 += __shfl_xor_sync(0xffffffffu, nrm2, off);
#pragma unroll
        for (int p = 0; p < PP; p++) dot[p] += __shfl_xor_sync(0xffffffffu, dot[p], off);
    }
    if (lane < PP) {
        float dl = 0.f;
#pragma unroll
        for (int p = 0; p < PP; p++) if (lane == p) dl = dot[p];
        float denom = fmaxf(sqrtf(nrm2), EPSF);
        float v = dl / denom;
        float c = fmaxf(v, 0.f);
        float n = c / fmaxf(SQRT_S * c, EPSF);
        g_n[((size_t)lane * BB + b) * SS + s] = n;
    }
}

// ---------------- kernel 2: softmax over s (per p,b) -> weights ----------------
__global__ __launch_bounds__(256) void ksoft() {
    __shared__ float sn[SS];
    __shared__ float red[256];
    int pb = blockIdx.x;
    int t = threadIdx.x;
    const float* np = g_n + (size_t)pb * SS;
    float m = -1e30f;
    for (int i = t; i < SS; i += 256) { float v = np[i]; sn[i] = v; m = fmaxf(m, v); }
    red[t] = m; __syncthreads();
    for (int o = 128; o; o >>= 1) { if (t < o) red[t] = fmaxf(red[t], red[t + o]); __syncthreads(); }
    m = red[0]; __syncthreads();
    float sum = 0.f;
    for (int i = t; i < SS; i += 256) sum += expf(sn[i] - m);
    red[t] = sum; __syncthreads();
    for (int o = 128; o; o >>= 1) { if (t < o) red[t] += red[t + o]; __syncthreads(); }
    float inv = 1.0f / red[0];
    for (int i = t; i < SS; i += 256) g_wsm[(size_t)pb * SS + i] = expf(sn[i] - m) * inv;
}

// ---------------- kernel 3: a_v partials: sum_s w[p,b,s] * ctx[b,s,d] ----------------
// 256 threads cover all D as float4. 32 s-rows per block, unrolled x4 for MLP.
__global__ __launch_bounds__(256) void kavp(const float* __restrict__ ctx) {
    __shared__ float ws[32 * PP];
    int schunk = blockIdx.x, b = blockIdx.y;
    int t = threadIdx.x;
    if (t < 32 * PP) {
        int sl = t >> 3, p = t & 7;
        ws[t] = g_wsm[((size_t)p * BB + b) * SS + schunk * 32 + sl];
    }
    __syncthreads();
    float4 acc[PP];
#pragma unroll
    for (int p = 0; p < PP; p++) acc[p] = make_float4(0.f, 0.f, 0.f, 0.f);
    const float4* cp = reinterpret_cast<const float4*>(ctx) +
                       ((size_t)b * SS + schunk * 32) * 256 + t;
#pragma unroll 2
    for (int sl = 0; sl < 32; sl += 4) {
        float4 x0 = cp[(size_t)(sl + 0) * 256];
        float4 x1 = cp[(size_t)(sl + 1) * 256];
        float4 x2 = cp[(size_t)(sl + 2) * 256];
        float4 x3 = cp[(size_t)(sl + 3) * 256];
#pragma unroll
        for (int p = 0; p < PP; p++) {
            float w0 = ws[(sl + 0) * 8 + p];
            float w1v = ws[(sl + 1) * 8 + p];
            float w2v = ws[(sl + 2) * 8 + p];
            float w3v = ws[(sl + 3) * 8 + p];
            acc[p].x += w0 * x0.x + w1v * x1.x + w2v * x2.x + w3v * x3.x;
            acc[p].y += w0 * x0.y + w1v * x1.y + w2v * x2.y + w3v * x3.y;
            acc[p].z += w0 * x0.z + w1v * x1.z + w2v * x2.z + w3v * x3.z;
            acc[p].w += w0 * x0.w + w1v * x1.w + w2v * x2.w + w3v * x3.w;
        }
    }
#pragma unroll
    for (int p = 0; p < PP; p++)
        reinterpret_cast<float4*>(g_avp)[(((size_t)schunk * PP + p) * BB + b) * 256 + t] = acc[p];
}

// ---------------- kernel 4: reduce partials ----------------
__global__ __launch_bounds__(256) void kavred() {
    int i = blockIdx.x * 256 + threadIdx.x;   // PP*BB*DD = 32768
    float s = 0.f;
#pragma unroll 8
    for (int c = 0; c < NSC; c++) s += g_avp[(size_t)c * PP * BB * DD + i];
    g_av[i] = s;
}

// ---------------- kernel 5: cos + double softmax -> gates ----------------
__global__ __launch_bounds__(1024) void kgate(const float* __restrict__ lora) {
    __shared__ float cs[PP * BB];
    int t = threadIdx.x, warp = t >> 5, lane = t & 31;
    int p = warp >> 2, b = warp & 3;
    float dot = 0.f, an2 = 0.f, en2 = 0.f;
    const float* e = lora + p * DD;
    const float* a = g_av + ((size_t)p * BB + b) * DD;
    for (int d = lane; d < DD; d += 32) {
        float ev = e[d], av = a[d];
        dot += ev * av; an2 += av * av; en2 += ev * ev;
    }
#pragma unroll
    for (int o = 16; o; o >>= 1) {
        dot += __shfl_xor_sync(0xffffffffu, dot, o);
        an2 += __shfl_xor_sync(0xffffffffu, an2, o);
        en2 += __shfl_xor_sync(0xffffffffu, en2, o);
    }
    if (lane == 0) cs[p * BB + b] = dot / fmaxf(sqrtf(en2) * sqrtf(an2), COSEPS);
    __syncthreads();
    if (t < BB) {
        int bb = t;
        float x[PP], m = -1e30f;
#pragma unroll
        for (int pp = 0; pp < PP; pp++) { x[pp] = cs[pp * BB + bb]; m = fmaxf(m, x[pp]); }
        float z = 0.f;
#pragma unroll
        for (int pp = 0; pp < PP; pp++) { x[pp] = expf(x[pp] - m); z += x[pp]; }
#pragma unroll
        for (int pp = 0; pp < PP; pp++) x[pp] /= z;      // s_t
        m = -1e30f;
#pragma unroll
        for (int pp = 0; pp < PP; pp++) m = fmaxf(m, x[pp]);
        z = 0.f;
#pragma unroll
        for (int pp = 0; pp < PP; pp++) { x[pp] = expf(x[pp] - m); z += x[pp]; }
#pragma unroll
        for (int pp = 0; pp < PP; pp++) g_gate[bb * PP + pp] = x[pp] / z;  // gate
    }
}

// ---------------- kernel 6: hbar[b,v,h] = sum_p gate * tanh(tok@w1 + b1) ----------------
__global__ __launch_bounds__(256) void khbar(const int* __restrict__ prefix,
                                             const float* __restrict__ tables,
                                             const float* __restrict__ b1) {
    __shared__ float tok[DD];
    int bv = blockIdx.x;
    int b = bv / VV;
    int t = threadIdx.x, warp = t >> 5, lane = t & 31;
    int pf = prefix[bv];
    float hacc[6];
#pragma unroll
    for (int j = 0; j < 6; j++) hacc[j] = 0.f;
    for (int p = 0; p < PP; p++) {
        __syncthreads();
        const float* src = tables + ((size_t)p * VV + pf) * DD;
        for (int i = t; i < DD; i += 256) tok[i] = src[i];
        __syncthreads();
        float gpb = g_gate[b * PP + p];
#pragma unroll
        for (int j = 0; j < 6; j++) {
            int h = warp + j * 8;
            if (h < HH) {
                const float4* wrow = reinterpret_cast<const float4*>(g_w1t + (size_t)h * DD);
                const float4* tk4 = reinterpret_cast<const float4*>(tok);
                float dot = 0.f;
#pragma unroll
                for (int it = 0; it < 8; it++) {
                    float4 wv = wrow[lane + it * 32];
                    float4 tv = tk4[lane + it * 32];
                    dot += wv.x * tv.x + wv.y * tv.y + wv.z * tv.z + wv.w * tv.w;
                }
#pragma unroll
                for (int o = 16; o; o >>= 1) dot += __shfl_xor_sync(0xffffffffu, dot, o);
                hacc[j] += gpb * tanhf(dot + b1[h]);
            }
        }
    }
    if (lane == 0) {
#pragma unroll
        for (int j = 0; j < 6; j++) {
            int h = warp + j * 8;
            if (h < HH) g_hbar[(size_t)bv * HH + h] = hacc[j];
        }
    }
}

// ---------------- kernel 7: out = hbar @ w2 + b2 (packed f32x2 FFMA2) ----------------
__device__ __forceinline__ unsigned long long fma2(unsigned long long a,
                                                   unsigned long long b,
                                                   unsigned long long c) {
    unsigned long long d;
    asm("fma.rn.f32x2 %0, %1, %2, %3;" : "=l"(d) : "l"(a), "l"(b), "l"(c));
    return d;
}

// 32 rows per block (blockIdx.y), 256 k per block (blockIdx.x). 128 threads.
__global__ __launch_bounds__(128) void kout(const float* __restrict__ w2,
                                            const float* __restrict__ b2,
                                            float* __restrict__ out) {
    __shared__ unsigned long long hb2[32 * HH];   // hbar duplicated {v,v}
    int r0 = blockIdx.y * 32;
    int t = threadIdx.x;
    for (int i = t; i < 32 * HH; i += 128) {
        float v = g_hbar[(size_t)(r0 + i / HH) * HH + (i % HH)];
        float2 d2 = make_float2(v, v);
        hb2[i] = *reinterpret_cast<unsigned long long*>(&d2);
    }
    __syncthreads();
    int kp = blockIdx.x * 256 + t * 2;
    unsigned long long wcol[HH];
#pragma unroll
    for (int h = 0; h < HH; h++) {
        float2 wv = *reinterpret_cast<const float2*>(w2 + (size_t)h * KK + kp);
        wcol[h] = *reinterpret_cast<unsigned long long*>(&wv);
    }
    float2 bv = *reinterpret_cast<const float2*>(b2 + kp);
    unsigned long long binit = *reinterpret_cast<unsigned long long*>(&bv);
    for (int rg = 0; rg < 32; rg += 4) {
        unsigned long long a0 = binit, a1 = binit, a2 = binit, a3 = binit;
#pragma unroll
        for (int h = 0; h < HH; h++) {
            a0 = fma2(wcol[h], hb2[(rg + 0) * HH + h], a0);
            a1 = fma2(wcol[h], hb2[(rg + 1) * HH + h], a1);
            a2 = fma2(wcol[h], hb2[(rg + 2) * HH + h], a2);
            a3 = fma2(wcol[h], hb2[(rg + 3) * HH + h], a3);
        }
        *reinterpret_cast<float2*>(out + (size_t)(r0 + rg + 0) * KK + kp) = *reinterpret_cast<float2*>(&a0);
        *reinterpret_cast<float2*>(out + (size_t)(r0 + rg + 1) * KK + kp) = *reinterpret_cast<float2*>(&a1);
        *reinterpret_cast<float2*>(out + (size_t)(r0 + rg + 2) * KK + kp) = *reinterpret_cast<float2*>(&a2);
        *reinterpret_cast<float2*>(out + (size_t)(r0 + rg + 3) * KK + kp) = *reinterpret_cast<float2*>(&a3);
    }
}

// ---------------- launcher ----------------
extern "C" void kernel_launch(void* const* d_in, const int* in_sizes, int n_in,
                              void* d_out, int out_size) {
    const int* prefix = nullptr;
    const float *ctx = nullptr, *tables = nullptr, *lora = nullptr;
    const float *w1 = nullptr, *b1 = nullptr, *w2 = nullptr, *b2 = nullptr;
    for (int i = 0; i < n_in; i++) {
        switch (in_sizes[i]) {
            case 256:     prefix = (const int*)d_in[i];   break;  // (B,V) int32
            case 8388608: ctx    = (const float*)d_in[i]; break;  // (B,S,D)
            case 524288:  tables = (const float*)d_in[i]; break;  // (P,V,D)
            case 8192:    lora   = (const float*)d_in[i]; break;  // (P,D)
            case 43008:   w1     = (const float*)d_in[i]; break;  // (D,H)
            case 42:      b1     = (const float*)d_in[i]; break;  // (H,)
            case 2064384: w2     = (const float*)d_in[i]; break;  // (H,K)
            case 49152:   b2     = (const float*)d_in[i]; break;  // (K,)
        }
    }
    float* out = (float*)d_out;

    kprep<<<168, 256>>>(lora, w1);
    knorm<<<1024, 256>>>(ctx);
    ksoft<<<32, 256>>>();
    kavp<<<dim3(NSC, 4), 256>>>(ctx);
    kavred<<<128, 256>>>();
    kgate<<<1, 1024>>>(lora);
    khbar<<<256, 256>>>(prefix, tables, b1);
    kout<<<dim3(KK / 256, 8), 128>>>(w2, b2, out);
}